// round 4
// baseline (speedup 1.0000x reference)
#include <cuda_runtime.h>
#include <math.h>

#define N_RES   500
#define N_SYSS  4
#define P_PAIRS 123256
#define NUM_W   52
#define BATCHN  256

typedef unsigned long long ull;

// scratch (device globals; no allocations allowed)
__device__ __align__(16) float g_alpha[P_PAIRS * 4];
__device__ __align__(16) float g_negiv[4];     // -1/max_alpha per subsystem

// ================= packed f32x2 helpers =================
__device__ __forceinline__ ull pk2(float a, float b) {
    ull r; asm("mov.b64 %0, {%1, %2};" : "=l"(r) : "f"(a), "f"(b)); return r;
}
__device__ __forceinline__ void upk2(float& a, float& b, ull v) {
    asm("mov.b64 {%0, %1}, %2;" : "=f"(a), "=f"(b) : "l"(v));
}
__device__ __forceinline__ ull fma2(ull a, ull b, ull c) {
    ull d; asm("fma.rn.f32x2 %0, %1, %2, %3;" : "=l"(d) : "l"(a), "l"(b), "l"(c)); return d;
}
__device__ __forceinline__ ull mul2(ull a, ull b) {
    ull d; asm("mul.rn.f32x2 %0, %1, %2;" : "=l"(d) : "l"(a), "l"(b)); return d;
}

// ================= setup kernel (weights -> alpha table + -1/max) =================
__global__ void k_setup(const float* __restrict__ weights) {
    __shared__ float ps[N_SYSS][NUM_W];
    __shared__ float w[N_RES][N_SYSS];
    int t = threadIdx.x;
    if (t < N_SYSS) {
        const float* row = weights + t * NUM_W;
        float m = row[0];
        for (int i = 1; i < NUM_W; i++) m = fmaxf(m, row[i]);
        float s = 0.0f;
        for (int i = 0; i < NUM_W; i++) s += expf(row[i] - m);
        float inv = 1.0f / s;
        for (int i = 0; i < NUM_W; i++) ps[t][i] = (expf(row[i] - m) * inv) * 52.0f;
    }
    __syncthreads();
    for (int r = t; r < N_RES; r += 256) {
        int b0 = r / 10;                       // SKIP=10, BALANCE=0
        float v[N_SYSS]; float sum = 2.5f;     // relu(FACTOR_FAKE - CUTOFF)
        #pragma unroll
        for (int n = 0; n < N_SYSS; n++) {
            float prod = (ps[n][b0] * ps[n][b0 + 1]) * ps[n][b0 + 2];
            v[n] = fmaxf(prod - 0.5f, 0.0f);
            sum += v[n];
        }
        #pragma unroll
        for (int n = 0; n < N_SYSS; n++) w[r][n] = v[n] / sum;
    }
    __syncthreads();

    // block 0: analytic column max of alpha via gap-4 prefix-max scan
    if (blockIdx.x == 0 && t < N_SYSS) {
        float pm = w[0][t];
        float best = 0.0f;
        for (int j = 4; j < N_RES; j++) {
            pm = fmaxf(pm, w[j - 4][t]);
            best = fmaxf(best, (pm * 5.0f) * (w[j][t] * 5.0f));
        }
        g_negiv[t] = -1.0f / best;
    }

    // alpha table slice for this block
    int p = blockIdx.x * 256 + t;
    if (p < P_PAIRS) {
        int i = (int)((993.0 - sqrt((double)(986049 - 8 * p))) * 0.5);
        if (i < 0) i = 0;
        while (i + 1 <= 495 && (496 * (i + 1) - ((i + 1) * i) / 2) <= p) i++;
        while (i > 0 && (496 * i - (i * (i - 1)) / 2) > p) i--;
        int j = p - (496 * i - (i * (i - 1)) / 2) + i + 4;
        float4 a;
        a.x = (w[i][0] * 5.0f) * (w[j][0] * 5.0f);
        a.y = (w[i][1] * 5.0f) * (w[j][1] * 5.0f);
        a.z = (w[i][2] * 5.0f) * (w[j][2] * 5.0f);
        a.w = (w[i][3] * 5.0f) * (w[j][3] * 5.0f);
        ((float4*)g_alpha)[p] = a;
    }
}

// ================= forced-IMAD helpers (`one` = opaque runtime 1) =================
__device__ __forceinline__ unsigned madd_r(unsigned a, unsigned one, unsigned b) {
    unsigned r; asm("mad.lo.u32 %0, %1, %2, %3;" : "=r"(r) : "r"(a), "r"(one), "r"(b)); return r;
}
template <unsigned K>
__device__ __forceinline__ unsigned madd_k(unsigned one, unsigned b) {
    unsigned r; asm("mad.lo.u32 %0, %1, %2, %3;" : "=r"(r) : "r"(one), "n"(K), "r"(b)); return r;
}
// rotate+xor on ALU: SHF + LOP3
template <int R>
__device__ __forceinline__ unsigned rot_s(unsigned x1, unsigned x0) {
    return __funnelshift_l(x1, x1, R) ^ x0;
}
// rotate+xor via FMA pipe: IMAD.WIDE (lo=x<<R, hi=x>>(32-R)) + LOP3 (lo|hi)^x0
template <int R>
__device__ __forceinline__ unsigned rot_w(unsigned x1, unsigned x0) {
    ull t;
    asm("mul.wide.u32 %0, %1, %2;" : "=l"(t) : "r"(x1), "n"(1u << R));
    unsigned lo = (unsigned)t;
    unsigned hi = (unsigned)(t >> 32);
    unsigned r;
    asm("lop3.b32 %0, %1, %2, %3, 0x56;" : "=r"(r) : "r"(lo), "r"(hi), "r"(x0));
    return r;     // (lo | hi) ^ x0
}

// threefry2x32, key (0,42), counter (0,c), partitionable fold (bit-identical to R1-R3)
__device__ __forceinline__ unsigned threefry_bits(unsigned c, unsigned one) {
    // ks0 = 0, ks1 = 42, ks2 = 0x1BD11BF0
    unsigned x1 = c + 42u;
    unsigned x0 = x1;                                   // round-1 add folded (x0 was 0)
    x1 = rot_s<13>(x1, x0);
    x0 = madd_r(x1, one, x0); x1 = rot_w<15>(x1, x0);
    x0 = madd_r(x1, one, x0); x1 = rot_s<26>(x1, x0);
    x0 = madd_r(x1, one, x0); x1 = rot_w< 6>(x1, x0);
    x1 = madd_k<0x1BD11BF1u>(one, x1);                  // ks2 + 1
    x0 = x0 + x1 + 42u;                                 // IADD3: x0 + ks1 + x1'
    x1 = rot_s<17>(x1, x0);
    x0 = madd_r(x1, one, x0); x1 = rot_w<29>(x1, x0);
    x0 = madd_r(x1, one, x0); x1 = rot_s<16>(x1, x0);
    x0 = madd_r(x1, one, x0); x1 = rot_w<24>(x1, x0);
    x1 = madd_k<2u>(one, x1);                           // ks0 + 2
    x0 = x0 + x1 + 0x1BD11BF0u;                         // IADD3: x0 + ks2 + x1'
    x1 = rot_s<13>(x1, x0);
    x0 = madd_r(x1, one, x0); x1 = rot_w<15>(x1, x0);
    x0 = madd_r(x1, one, x0); x1 = rot_s<26>(x1, x0);
    x0 = madd_r(x1, one, x0); x1 = rot_w< 6>(x1, x0);
    x1 = madd_k<45u>(one, x1);                          // ks1 + 3
    x0 = x0 + x1;                                       // x0 + ks0(0) + x1'
    x1 = rot_s<17>(x1, x0);
    x0 = madd_r(x1, one, x0); x1 = rot_w<29>(x1, x0);
    x0 = madd_r(x1, one, x0); x1 = rot_s<16>(x1, x0);
    x0 = madd_r(x1, one, x0); x1 = rot_w<24>(x1, x0);
    x1 = madd_k<0x1BD11BF4u>(one, x1);                  // ks2 + 4
    x0 = x0 + x1 + 42u;                                 // IADD3: x0 + ks1 + x1'
    x1 = rot_s<13>(x1, x0);
    x0 = madd_r(x1, one, x0); x1 = rot_w<15>(x1, x0);
    x0 = madd_r(x1, one, x0); x1 = rot_s<26>(x1, x0);
    x0 = madd_r(x1, one, x0); x1 = rot_w< 6>(x1, x0);
    x0 = madd_k<0x1BD11BF0u>(one, x0);                  // ks2
    x1 = madd_k<5u>(one, x1);                           // ks0 + 5
    return x0 ^ x1;
}

// rare tail of Giles erfinv (w >= 5), coeffs pre-scaled by sqrt(2)/2
__device__ __noinline__ float tail_fix(float u, float l) {
    float w = l * -0.693147180559945f;
    float s = sqrtf(w) - 3.0f;
    float p =          -1.415729e-04f;
    p = fmaf(p, s,  7.138285e-05f);
    p = fmaf(p, s,  9.541345e-04f);
    p = fmaf(p, s, -2.597603e-03f);
    p = fmaf(p, s,  4.058407e-03f);
    p = fmaf(p, s, -5.389894e-03f);
    p = fmaf(p, s,  6.674289e-03f);
    p = fmaf(p, s,  7.082905e-01f);
    p = fmaf(p, s,  2.0032171f);
    return u * p;
}

#define LCUT (-7.21347520444482f)   // l <= LCUT  <=>  w = -ln(1-u^2) >= 5

// ================= main kernel: 8 outputs (2 float4) per thread =================
__global__ void __launch_bounds__(256) k_main(
    const float*  __restrict__ x,
    const float*  __restrict__ mean,
    const float*  __restrict__ stdv,
    float4*       __restrict__ out,
    unsigned one)
{
    unsigned gtid = blockIdx.x * 256u + threadIdx.x;
    unsigned pos  = gtid * 2u;                 // (b,p) position of first float4
    unsigned p0   = pos % (unsigned)P_PAIRS;   // p0 even, p1 = p0+1 (P even, no wrap)

    float2 xv = *(const float2*)(x + pos);
    float2 mu = __ldg((const float2*)(mean + p0));
    float2 sd = __ldg((const float2*)(stdv + p0));
    float xn0 = __fdividef(xv.x - mu.x, sd.x);
    float xn1 = __fdividef(xv.y - mu.y, sd.y);

    float4 niv4 = *(const float4*)g_negiv;
    ull NIV01 = pk2(niv4.x, niv4.y);
    ull NIV23 = pk2(niv4.z, niv4.w);
    const ull ONE2 = pk2(1.0f, 1.0f);
    const ull C8 = pk2( 1.987138e-08f,  1.987138e-08f);
    const ull C7 = pk2( 2.427323e-07f,  2.427323e-07f);
    const ull C6 = pk2(-2.491411e-06f, -2.491411e-06f);
    const ull C5 = pk2(-3.105282e-06f, -3.105282e-06f);
    const ull C4 = pk2( 1.545603e-04f,  1.545603e-04f);
    const ull C3 = pk2(-8.865218e-04f, -8.865218e-04f);
    const ull C2 = pk2(-2.954063e-03f, -2.954063e-03f);
    const ull C1 = pk2( 1.7440262e-01f, 1.7440262e-01f);
    const ull C0 = pk2( 1.0616583f,     1.0616583f);

    unsigned base = pos * 4u;

    #pragma unroll
    for (int g = 0; g < 2; g++) {               // two float4 groups
        unsigned pg = p0 + (unsigned)g;
        float xn = g ? xn1 : xn0;
        ull XN = pk2(xn, xn);
        const float4 a4 = __ldg((const float4*)g_alpha + pg);
        ull A01 = pk2(a4.x, a4.y);
        ull A23 = pk2(a4.z, a4.w);

        unsigned c0 = base + (unsigned)(4 * g);
        unsigned b0 = threefry_bits(c0 + 0u, one);
        unsigned b1 = threefry_bits(c0 + 1u, one);
        unsigned b2 = threefry_bits(c0 + 2u, one);
        unsigned b3 = threefry_bits(c0 + 3u, one);

        ull R[2];
        #pragma unroll
        for (int h = 0; h < 2; h++) {           // two packed pairs per float4
            unsigned ba = h ? b2 : b0;
            unsigned bb = h ? b3 : b1;
            // scalar uniform mapping: g = 1 + m*2^-23 via IMAD (OR == ADD, m < 2^23)
            float ga = __uint_as_float(madd_k<0x3f800000u>(one, ba >> 9));
            float gb = __uint_as_float(madd_k<0x3f800000u>(one, bb >> 9));
            float fa = ga - 1.0f;                         // exact
            float fb = gb - 1.0f;
            float u0 = fmaf(fa, 2.0f, -0.99999994f);      // u in (-1,1), bit-exact to JAX
            float u1 = fmaf(fb, 2.0f, -0.99999994f);
            float t0 = fmaf(-u0, u0, 1.0f);               // 1 - u^2
            float t1 = fmaf(-u1, u1, 1.0f);
            float l0 = __log2f(t0);
            float l1 = __log2f(t1);
            float s0 = fmaf(l0, -0.693147180559945f, -2.5f);  // s = w - 2.5
            float s1 = fmaf(l1, -0.693147180559945f, -2.5f);
            ull S = pk2(s0, s1);
            ull P = fma2(C8, S, C7);
            P = fma2(P, S, C6);
            P = fma2(P, S, C5);
            P = fma2(P, S, C4);
            P = fma2(P, S, C3);
            P = fma2(P, S, C2);
            P = fma2(P, S, C1);
            P = fma2(P, S, C0);
            ull U = pk2(u0, u1);
            ull Rp = mul2(U, P);                // 0.5 * normal (coeffs pre-scaled)
            if (l0 <= LCUT || l1 <= LCUT) {     // rare tail (~0.7% of pairs)
                float r0, r1; upk2(r0, r1, Rp);
                if (l0 <= LCUT) r0 = tail_fix(u0, l0);
                if (l1 <= LCUT) r1 = tail_fix(u1, l1);
                Rp = pk2(r0, r1);
            }
            ull A  = h ? A23 : A01;
            ull NI = h ? NIV23 : NIV01;
            ull Q  = fma2(A, NI, ONE2);         // 1 - a/max
            R[h] = fma2(XN, A, mul2(Q, Rp));    // xn*a + q*(0.5*normal)
        }
        float4 o;
        upk2(o.x, o.y, R[0]);
        upk2(o.z, o.w, R[1]);
        out[pos + (unsigned)g] = o;
    }
}

// ================= launch =================
extern "C" void kernel_launch(void* const* d_in, const int* in_sizes, int n_in,
                              void* d_out, int out_size)
{
    const float* x       = (const float*)d_in[0];
    const float* mean    = (const float*)d_in[1];
    const float* stdv    = (const float*)d_in[2];
    const float* weights = (const float*)d_in[3];

    k_setup<<<(P_PAIRS + 255) / 256, 256>>>(weights);
    k_main<<<(BATCHN * P_PAIRS / 2) / 256, 256>>>(x, mean, stdv, (float4*)d_out, 1u);
    (void)in_sizes; (void)n_in; (void)out_size;
}

// round 5
// speedup vs baseline: 1.1628x; 1.1628x over previous
#include <cuda_runtime.h>
#include <math.h>

#define N_RES   500
#define N_SYSS  4
#define P_PAIRS 123256
#define NUM_W   52
#define BATCHN  256

typedef unsigned long long ull;

// scratch (device globals; no allocations allowed)
__device__ __align__(16) float g_alpha[P_PAIRS * 4];
__device__ __align__(16) float g_negiv[4];     // -1/max_alpha per subsystem

// ================= packed f32x2 helpers =================
__device__ __forceinline__ ull pk2(float a, float b) {
    ull r; asm("mov.b64 %0, {%1, %2};" : "=l"(r) : "f"(a), "f"(b)); return r;
}
__device__ __forceinline__ void upk2(float& a, float& b, ull v) {
    asm("mov.b64 {%0, %1}, %2;" : "=f"(a), "=f"(b) : "l"(v));
}
__device__ __forceinline__ ull fma2(ull a, ull b, ull c) {
    ull d; asm("fma.rn.f32x2 %0, %1, %2, %3;" : "=l"(d) : "l"(a), "l"(b), "l"(c)); return d;
}
__device__ __forceinline__ ull mul2(ull a, ull b) {
    ull d; asm("mul.rn.f32x2 %0, %1, %2;" : "=l"(d) : "l"(a), "l"(b)); return d;
}
__device__ __forceinline__ ull add2(ull a, ull b) {
    ull d; asm("add.rn.f32x2 %0, %1, %2;" : "=l"(d) : "l"(a), "l"(b)); return d;
}

// ================= setup kernel (weights -> alpha table + -1/max) =================
__global__ void k_setup(const float* __restrict__ weights) {
    __shared__ float ps[N_SYSS][NUM_W];
    __shared__ float w[N_RES][N_SYSS];
    int t = threadIdx.x;
    if (t < N_SYSS) {
        const float* row = weights + t * NUM_W;
        float m = row[0];
        for (int i = 1; i < NUM_W; i++) m = fmaxf(m, row[i]);
        float s = 0.0f;
        for (int i = 0; i < NUM_W; i++) s += expf(row[i] - m);
        float inv = 1.0f / s;
        for (int i = 0; i < NUM_W; i++) ps[t][i] = (expf(row[i] - m) * inv) * 52.0f;
    }
    __syncthreads();
    for (int r = t; r < N_RES; r += 256) {
        int b0 = r / 10;                       // SKIP=10, BALANCE=0
        float v[N_SYSS]; float sum = 2.5f;     // relu(FACTOR_FAKE - CUTOFF)
        #pragma unroll
        for (int n = 0; n < N_SYSS; n++) {
            float prod = (ps[n][b0] * ps[n][b0 + 1]) * ps[n][b0 + 2];
            v[n] = fmaxf(prod - 0.5f, 0.0f);
            sum += v[n];
        }
        #pragma unroll
        for (int n = 0; n < N_SYSS; n++) w[r][n] = v[n] / sum;
    }
    __syncthreads();

    // block 0: analytic column max of alpha via gap-4 prefix-max scan
    if (blockIdx.x == 0 && t < N_SYSS) {
        float pm = w[0][t];
        float best = 0.0f;
        for (int j = 4; j < N_RES; j++) {
            pm = fmaxf(pm, w[j - 4][t]);
            best = fmaxf(best, (pm * 5.0f) * (w[j][t] * 5.0f));
        }
        g_negiv[t] = -1.0f / best;
    }

    // alpha table slice for this block
    int p = blockIdx.x * 256 + t;
    if (p < P_PAIRS) {
        int i = (int)((993.0 - sqrt((double)(986049 - 8 * p))) * 0.5);
        if (i < 0) i = 0;
        while (i + 1 <= 495 && (496 * (i + 1) - ((i + 1) * i) / 2) <= p) i++;
        while (i > 0 && (496 * i - (i * (i - 1)) / 2) > p) i--;
        int j = p - (496 * i - (i * (i - 1)) / 2) + i + 4;
        float4 a;
        a.x = (w[i][0] * 5.0f) * (w[j][0] * 5.0f);
        a.y = (w[i][1] * 5.0f) * (w[j][1] * 5.0f);
        a.z = (w[i][2] * 5.0f) * (w[j][2] * 5.0f);
        a.w = (w[i][3] * 5.0f) * (w[j][3] * 5.0f);
        ((float4*)g_alpha)[p] = a;
    }
}

// ================= forced-IMAD helpers (`one` = opaque runtime 1) =================
__device__ __forceinline__ unsigned madd_r(unsigned a, unsigned one, unsigned b) {
    unsigned r; asm("mad.lo.u32 %0, %1, %2, %3;" : "=r"(r) : "r"(a), "r"(one), "r"(b)); return r;
}
template <unsigned K>
__device__ __forceinline__ unsigned madd_k(unsigned one, unsigned b) {
    unsigned r; asm("mad.lo.u32 %0, %1, %2, %3;" : "=r"(r) : "r"(one), "n"(K), "r"(b)); return r;
}
// volatile variant: defeats CSE so x0/x1 init are two independent FMA-pipe ops (no MOV)
template <unsigned K>
__device__ __forceinline__ unsigned madd_kv(unsigned one, unsigned b) {
    unsigned r; asm volatile("mad.lo.u32 %0, %1, %2, %3;" : "=r"(r) : "r"(one), "n"(K), "r"(b)); return r;
}
__device__ __forceinline__ unsigned rotxor(unsigned x1, int r, unsigned x0) {
    return __funnelshift_l(x1, x1, r) ^ x0;     // SHF + LOP3 (alu)
}

// threefry2x32, key (0,42), counter (0, c0+CNT), partitionable fold (bit-identical to R1/R3)
template <unsigned CNT>
__device__ __forceinline__ unsigned threefry_bits(unsigned c0, unsigned one) {
    // ks0 = 0, ks1 = 42, ks2 = 0x1BD11BF0
    unsigned x1 = madd_k <CNT + 42u>(one, c0);          // x1 = c + ks1 (fma)
    unsigned x0 = madd_kv<CNT + 42u>(one, c0);          // x0 = same value, independent op (fma)
    x1 = rotxor(x1, 13, x0);
    x0 = madd_r(x1, one, x0); x1 = rotxor(x1, 15, x0);
    x0 = madd_r(x1, one, x0); x1 = rotxor(x1, 26, x0);
    x0 = madd_r(x1, one, x0); x1 = rotxor(x1,  6, x0);
    x0 = madd_k<42u>(one, x0);          x1 = madd_k<0x1BD11BF1u>(one, x1);
    x0 = madd_r(x1, one, x0); x1 = rotxor(x1, 17, x0);
    x0 = madd_r(x1, one, x0); x1 = rotxor(x1, 29, x0);
    x0 = madd_r(x1, one, x0); x1 = rotxor(x1, 16, x0);
    x0 = madd_r(x1, one, x0); x1 = rotxor(x1, 24, x0);
    x0 = madd_k<0x1BD11BF0u>(one, x0);  x1 = madd_k<2u>(one, x1);
    x0 = madd_r(x1, one, x0); x1 = rotxor(x1, 13, x0);
    x0 = madd_r(x1, one, x0); x1 = rotxor(x1, 15, x0);
    x0 = madd_r(x1, one, x0); x1 = rotxor(x1, 26, x0);
    x0 = madd_r(x1, one, x0); x1 = rotxor(x1,  6, x0);
                                        x1 = madd_k<45u>(one, x1);
    x0 = madd_r(x1, one, x0); x1 = rotxor(x1, 17, x0);
    x0 = madd_r(x1, one, x0); x1 = rotxor(x1, 29, x0);
    x0 = madd_r(x1, one, x0); x1 = rotxor(x1, 16, x0);
    x0 = madd_r(x1, one, x0); x1 = rotxor(x1, 24, x0);
    x0 = madd_k<42u>(one, x0);          x1 = madd_k<0x1BD11BF4u>(one, x1);
    x0 = madd_r(x1, one, x0); x1 = rotxor(x1, 13, x0);
    x0 = madd_r(x1, one, x0); x1 = rotxor(x1, 15, x0);
    x0 = madd_r(x1, one, x0); x1 = rotxor(x1, 26, x0);
    x0 = madd_r(x1, one, x0); x1 = rotxor(x1,  6, x0);
    x0 = madd_k<0x1BD11BF0u>(one, x0);  x1 = madd_k<5u>(one, x1);
    return x0 ^ x1;
}

// rare tail of Giles erfinv (w >= 5), coeffs pre-scaled by sqrt(2)/2
__device__ __noinline__ float tail_fix(float u, float l) {
    float w = l * -0.693147180559945f;
    float s = sqrtf(w) - 3.0f;
    float p =          -1.415729e-04f;
    p = fmaf(p, s,  7.138285e-05f);
    p = fmaf(p, s,  9.541345e-04f);
    p = fmaf(p, s, -2.597603e-03f);
    p = fmaf(p, s,  4.058407e-03f);
    p = fmaf(p, s, -5.389894e-03f);
    p = fmaf(p, s,  6.674289e-03f);
    p = fmaf(p, s,  7.082905e-01f);
    p = fmaf(p, s,  2.0032171f);
    return u * p;
}

#define LCUT (-7.21347520444482f)   // l <= LCUT  <=>  w = -ln(1-u^2) >= 5

// ================= main kernel: 8 outputs (2 float4) per thread =================
__global__ void __launch_bounds__(256, 4) k_main(
    const float*  __restrict__ x,
    const float*  __restrict__ mean,
    const float*  __restrict__ stdv,
    float4*       __restrict__ out,
    unsigned one)
{
    unsigned gtid = blockIdx.x * 256u + threadIdx.x;
    unsigned pos  = gtid * 2u;                 // (b,p) position of first float4
    unsigned p0   = pos % (unsigned)P_PAIRS;   // p0 even, p1 = p0+1 (P even, no wrap)

    float2 xv = *(const float2*)(x + pos);
    float2 mu = __ldg((const float2*)(mean + p0));
    float2 sd = __ldg((const float2*)(stdv + p0));
    float xn0 = __fdividef(xv.x - mu.x, sd.x);
    float xn1 = __fdividef(xv.y - mu.y, sd.y);

    float4 niv4 = *(const float4*)g_negiv;
    ull NIV01 = pk2(niv4.x, niv4.y);
    ull NIV23 = pk2(niv4.z, niv4.w);
    const ull NLN2 = pk2(-0.693147180559945f, -0.693147180559945f);
    const ull M2_5 = pk2(-2.5f, -2.5f);
    const ull ONE2 = pk2(1.0f, 1.0f);
    const ull C8 = pk2( 1.987138e-08f,  1.987138e-08f);
    const ull C7 = pk2( 2.427323e-07f,  2.427323e-07f);
    const ull C6 = pk2(-2.491411e-06f, -2.491411e-06f);
    const ull C5 = pk2(-3.105282e-06f, -3.105282e-06f);
    const ull C4 = pk2( 1.545603e-04f,  1.545603e-04f);
    const ull C3 = pk2(-8.865218e-04f, -8.865218e-04f);
    const ull C2 = pk2(-2.954063e-03f, -2.954063e-03f);
    const ull C1 = pk2( 1.7440262e-01f, 1.7440262e-01f);
    const ull C0 = pk2( 1.0616583f,     1.0616583f);

    unsigned base = pos * 4u;                  // counter base for this thread

    #pragma unroll
    for (int g = 0; g < 2; g++) {               // two float4 groups
        unsigned pg = p0 + (unsigned)g;
        float xn = g ? xn1 : xn0;
        ull XN = pk2(xn, xn);
        const float4 a4 = __ldg((const float4*)g_alpha + pg);
        ull A01 = pk2(a4.x, a4.y);
        ull A23 = pk2(a4.z, a4.w);

        unsigned b0, b1, b2, b3;
        if (g == 0) {
            b0 = threefry_bits<0u>(base, one);
            b1 = threefry_bits<1u>(base, one);
            b2 = threefry_bits<2u>(base, one);
            b3 = threefry_bits<3u>(base, one);
        } else {
            b0 = threefry_bits<4u>(base, one);
            b1 = threefry_bits<5u>(base, one);
            b2 = threefry_bits<6u>(base, one);
            b3 = threefry_bits<7u>(base, one);
        }

        ull R[2];
        #pragma unroll
        for (int h = 0; h < 2; h++) {           // two packed pairs per float4
            unsigned ba = h ? b2 : b0;
            unsigned bb = h ? b3 : b1;
            // uniform mapping: g = 1 + m*2^-23 via IMAD (OR == ADD, m < 2^23)
            float ga = __uint_as_float(madd_k<0x3f800000u>(one, ba >> 9));
            float gb = __uint_as_float(madd_k<0x3f800000u>(one, bb >> 9));
            float fa = ga - 1.0f;                         // exact
            float fb = gb - 1.0f;
            float u0 = fmaf(fa, 2.0f, -0.99999994f);      // u in (-1,1), bit-exact to JAX
            float u1 = fmaf(fb, 2.0f, -0.99999994f);
            float t0 = fmaf(-u0, u0, 1.0f);               // 1 - u^2
            float t1 = fmaf(-u1, u1, 1.0f);
            float l0 = __log2f(t0);
            float l1 = __log2f(t1);
            ull W = pk2(l0, l1);
            ull S = fma2(W, NLN2, M2_5);        // s = -ln2*l - 2.5
            ull P = fma2(C8, S, C7);
            P = fma2(P, S, C6);
            P = fma2(P, S, C5);
            P = fma2(P, S, C4);
            P = fma2(P, S, C3);
            P = fma2(P, S, C2);
            P = fma2(P, S, C1);
            P = fma2(P, S, C0);
            ull U = pk2(u0, u1);
            ull Rp = mul2(U, P);                // 0.5 * normal (coeffs pre-scaled)
            if (l0 <= LCUT || l1 <= LCUT) {     // rare tail (~0.7% of pairs)
                float r0, r1; upk2(r0, r1, Rp);
                if (l0 <= LCUT) r0 = tail_fix(u0, l0);
                if (l1 <= LCUT) r1 = tail_fix(u1, l1);
                Rp = pk2(r0, r1);
            }
            ull A  = h ? A23 : A01;
            ull NI = h ? NIV23 : NIV01;
            ull Q  = fma2(A, NI, ONE2);         // 1 - a/max
            R[h] = fma2(XN, A, mul2(Q, Rp));    // xn*a + q*(0.5*normal)
        }
        float4 o;
        upk2(o.x, o.y, R[0]);
        upk2(o.z, o.w, R[1]);
        out[pos + (unsigned)g] = o;
    }
}

// ================= launch =================
extern "C" void kernel_launch(void* const* d_in, const int* in_sizes, int n_in,
                              void* d_out, int out_size)
{
    const float* x       = (const float*)d_in[0];
    const float* mean    = (const float*)d_in[1];
    const float* stdv    = (const float*)d_in[2];
    const float* weights = (const float*)d_in[3];

    k_setup<<<(P_PAIRS + 255) / 256, 256>>>(weights);
    k_main<<<(BATCHN * P_PAIRS / 2) / 256, 256>>>(x, mean, stdv, (float4*)d_out, 1u);
    (void)in_sizes; (void)n_in; (void)out_size;
}

// round 6
// speedup vs baseline: 1.2034x; 1.0349x over previous
#include <cuda_runtime.h>
#include <math.h>

#define N_RES   500
#define N_SYSS  4
#define P_PAIRS 123256
#define NUM_W   52
#define BATCHN  256

typedef unsigned long long ull;

// scratch (device globals; no allocations allowed)
__device__ __align__(16) float g_alpha[P_PAIRS * 4];
__device__ __align__(16) float g_negiv[4];     // -1/max_alpha per subsystem

// ================= packed f32x2 helpers =================
__device__ __forceinline__ ull pk2(float a, float b) {
    ull r; asm("mov.b64 %0, {%1, %2};" : "=l"(r) : "f"(a), "f"(b)); return r;
}
__device__ __forceinline__ void upk2(float& a, float& b, ull v) {
    asm("mov.b64 {%0, %1}, %2;" : "=f"(a), "=f"(b) : "l"(v));
}
__device__ __forceinline__ ull fma2(ull a, ull b, ull c) {
    ull d; asm("fma.rn.f32x2 %0, %1, %2, %3;" : "=l"(d) : "l"(a), "l"(b), "l"(c)); return d;
}
__device__ __forceinline__ ull mul2(ull a, ull b) {
    ull d; asm("mul.rn.f32x2 %0, %1, %2;" : "=l"(d) : "l"(a), "l"(b)); return d;
}

// ================= setup kernel (weights -> alpha table + -1/max) =================
__global__ void k_setup(const float* __restrict__ weights) {
    __shared__ float ps[N_SYSS][NUM_W];
    __shared__ float w[N_RES][N_SYSS];
    int t = threadIdx.x;
    if (t < N_SYSS) {
        const float* row = weights + t * NUM_W;
        float m = row[0];
        for (int i = 1; i < NUM_W; i++) m = fmaxf(m, row[i]);
        float s = 0.0f;
        for (int i = 0; i < NUM_W; i++) s += expf(row[i] - m);
        float inv = 1.0f / s;
        for (int i = 0; i < NUM_W; i++) ps[t][i] = (expf(row[i] - m) * inv) * 52.0f;
    }
    __syncthreads();
    for (int r = t; r < N_RES; r += 256) {
        int b0 = r / 10;                       // SKIP=10, BALANCE=0
        float v[N_SYSS]; float sum = 2.5f;     // relu(FACTOR_FAKE - CUTOFF)
        #pragma unroll
        for (int n = 0; n < N_SYSS; n++) {
            float prod = (ps[n][b0] * ps[n][b0 + 1]) * ps[n][b0 + 2];
            v[n] = fmaxf(prod - 0.5f, 0.0f);
            sum += v[n];
        }
        #pragma unroll
        for (int n = 0; n < N_SYSS; n++) w[r][n] = v[n] / sum;
    }
    __syncthreads();

    // block 0: analytic column max of alpha via gap-4 prefix-max scan
    if (blockIdx.x == 0 && t < N_SYSS) {
        float pm = w[0][t];
        float best = 0.0f;
        for (int j = 4; j < N_RES; j++) {
            pm = fmaxf(pm, w[j - 4][t]);
            best = fmaxf(best, (pm * 5.0f) * (w[j][t] * 5.0f));
        }
        g_negiv[t] = -1.0f / best;
    }

    // alpha table slice for this block
    int p = blockIdx.x * 256 + t;
    if (p < P_PAIRS) {
        int i = (int)((993.0 - sqrt((double)(986049 - 8 * p))) * 0.5);
        if (i < 0) i = 0;
        while (i + 1 <= 495 && (496 * (i + 1) - ((i + 1) * i) / 2) <= p) i++;
        while (i > 0 && (496 * i - (i * (i - 1)) / 2) > p) i--;
        int j = p - (496 * i - (i * (i - 1)) / 2) + i + 4;
        float4 a;
        a.x = (w[i][0] * 5.0f) * (w[j][0] * 5.0f);
        a.y = (w[i][1] * 5.0f) * (w[j][1] * 5.0f);
        a.z = (w[i][2] * 5.0f) * (w[j][2] * 5.0f);
        a.w = (w[i][3] * 5.0f) * (w[j][3] * 5.0f);
        ((float4*)g_alpha)[p] = a;
    }
}

// ================= forced-IMAD helpers (`one` = opaque runtime 1) =================
__device__ __forceinline__ unsigned madd_r(unsigned a, unsigned one, unsigned b) {
    unsigned r; asm("mad.lo.u32 %0, %1, %2, %3;" : "=r"(r) : "r"(a), "r"(one), "r"(b)); return r;
}
template <unsigned K>
__device__ __forceinline__ unsigned madd_k(unsigned one, unsigned b) {
    unsigned r; asm("mad.lo.u32 %0, %1, %2, %3;" : "=r"(r) : "r"(one), "n"(K), "r"(b)); return r;
}
__device__ __forceinline__ unsigned rotxor(unsigned x1, int r, unsigned x0) {
    return __funnelshift_l(x1, x1, r) ^ x0;     // SHF + LOP3 (alu)
}
// bits -> float-mantissa mapping in ONE op: hi(bits * 2^23) + 0x3f800000 = (bits>>9) | 1.0f
__device__ __forceinline__ float map_g(unsigned bits) {
    unsigned r;
    asm("mad.hi.u32 %0, %1, %2, %3;" : "=r"(r)
        : "r"(bits), "r"(0x00800000u), "r"(0x3f800000u));
    return __uint_as_float(r);
}

// threefry2x32, key (0,42), counter (0, c0+CNT), partitionable fold (bit-identical to R1/R3/R5)
template <unsigned CNT>
__device__ __forceinline__ unsigned threefry_bits(unsigned c0, unsigned one) {
    // ks0 = 0, ks1 = 42, ks2 = 0x1BD11BF0
    unsigned t  = madd_k<CNT + 42u>(one, c0);       // t = c + ks1 = x1_init = x0 after round 1
    unsigned x1 = __funnelshift_l(t, t, 13) ^ t;    // round-1 rot (x0 == x1_init == t)
    unsigned x0 = t;                                // no instruction
    x0 = madd_r(x1, one, x0); x1 = rotxor(x1, 15, x0);
    x0 = madd_r(x1, one, x0); x1 = rotxor(x1, 26, x0);
    x0 = madd_r(x1, one, x0); x1 = rotxor(x1,  6, x0);
    x0 = madd_k<42u>(one, x0);          x1 = madd_k<0x1BD11BF1u>(one, x1);
    x0 = madd_r(x1, one, x0); x1 = rotxor(x1, 17, x0);
    x0 = madd_r(x1, one, x0); x1 = rotxor(x1, 29, x0);
    x0 = madd_r(x1, one, x0); x1 = rotxor(x1, 16, x0);
    x0 = madd_r(x1, one, x0); x1 = rotxor(x1, 24, x0);
    x0 = madd_k<0x1BD11BF0u>(one, x0);  x1 = madd_k<2u>(one, x1);
    x0 = madd_r(x1, one, x0); x1 = rotxor(x1, 13, x0);
    x0 = madd_r(x1, one, x0); x1 = rotxor(x1, 15, x0);
    x0 = madd_r(x1, one, x0); x1 = rotxor(x1, 26, x0);
    x0 = madd_r(x1, one, x0); x1 = rotxor(x1,  6, x0);
                                        x1 = madd_k<45u>(one, x1);
    x0 = madd_r(x1, one, x0); x1 = rotxor(x1, 17, x0);
    x0 = madd_r(x1, one, x0); x1 = rotxor(x1, 29, x0);
    x0 = madd_r(x1, one, x0); x1 = rotxor(x1, 16, x0);
    x0 = madd_r(x1, one, x0); x1 = rotxor(x1, 24, x0);
    x0 = madd_k<42u>(one, x0);          x1 = madd_k<0x1BD11BF4u>(one, x1);
    x0 = madd_r(x1, one, x0); x1 = rotxor(x1, 13, x0);
    x0 = madd_r(x1, one, x0); x1 = rotxor(x1, 15, x0);
    x0 = madd_r(x1, one, x0); x1 = rotxor(x1, 26, x0);
    x0 = madd_r(x1, one, x0); x1 = rotxor(x1,  6, x0);
    x0 = madd_k<0x1BD11BF0u>(one, x0);  x1 = madd_k<5u>(one, x1);
    return x0 ^ x1;
}

// rare tail of Giles erfinv (w >= 5), coeffs pre-scaled by sqrt(2)/2
__device__ __noinline__ float tail_fix(float u, float l) {
    float w = l * -0.693147180559945f;
    float s = sqrtf(w) - 3.0f;
    float p =          -1.415729e-04f;
    p = fmaf(p, s,  7.138285e-05f);
    p = fmaf(p, s,  9.541345e-04f);
    p = fmaf(p, s, -2.597603e-03f);
    p = fmaf(p, s,  4.058407e-03f);
    p = fmaf(p, s, -5.389894e-03f);
    p = fmaf(p, s,  6.674289e-03f);
    p = fmaf(p, s,  7.082905e-01f);
    p = fmaf(p, s,  2.0032171f);
    return u * p;
}

#define LCUT (-7.21347520444482f)   // l <= LCUT  <=>  w = -ln(1-u^2) >= 5

// ================= one float4 group (4 outputs) =================
template <unsigned G>
__device__ __forceinline__ void do_group(
    unsigned base, unsigned one, unsigned p0, float xn,
    ull NIV01, ull NIV23, float4* __restrict__ out, unsigned pos)
{
    const ull NLN2 = pk2(-0.693147180559945f, -0.693147180559945f);
    const ull M2_5 = pk2(-2.5f, -2.5f);
    const ull ONE2 = pk2(1.0f, 1.0f);
    const ull C8 = pk2( 1.987138e-08f,  1.987138e-08f);
    const ull C7 = pk2( 2.427323e-07f,  2.427323e-07f);
    const ull C6 = pk2(-2.491411e-06f, -2.491411e-06f);
    const ull C5 = pk2(-3.105282e-06f, -3.105282e-06f);
    const ull C4 = pk2( 1.545603e-04f,  1.545603e-04f);
    const ull C3 = pk2(-8.865218e-04f, -8.865218e-04f);
    const ull C2 = pk2(-2.954063e-03f, -2.954063e-03f);
    const ull C1 = pk2( 1.7440262e-01f, 1.7440262e-01f);
    const ull C0 = pk2( 1.0616583f,     1.0616583f);

    const float4 a4 = __ldg((const float4*)g_alpha + (p0 + G));
    ull A01 = pk2(a4.x, a4.y);
    ull A23 = pk2(a4.z, a4.w);
    ull XN = pk2(xn, xn);

    unsigned b0 = threefry_bits<4u * G + 0u>(base, one);
    unsigned b1 = threefry_bits<4u * G + 1u>(base, one);
    unsigned b2 = threefry_bits<4u * G + 2u>(base, one);
    unsigned b3 = threefry_bits<4u * G + 3u>(base, one);

    ull R[2];
    #pragma unroll
    for (int h = 0; h < 2; h++) {
        unsigned ba = h ? b2 : b0;
        unsigned bb = h ? b3 : b1;
        float ga = map_g(ba);                         // 1 + m*2^-23, single IMAD.HI
        float gb = map_g(bb);
        float fa = ga - 1.0f;                         // exact
        float fb = gb - 1.0f;
        float u0 = fmaf(fa, 2.0f, -0.99999994f);      // u in (-1,1), bit-exact to JAX
        float u1 = fmaf(fb, 2.0f, -0.99999994f);
        float t0 = fmaf(-u0, u0, 1.0f);               // 1 - u^2
        float t1 = fmaf(-u1, u1, 1.0f);
        float l0 = __log2f(t0);
        float l1 = __log2f(t1);
        ull W = pk2(l0, l1);
        ull S = fma2(W, NLN2, M2_5);        // s = -ln2*l - 2.5
        ull P = fma2(C8, S, C7);
        P = fma2(P, S, C6);
        P = fma2(P, S, C5);
        P = fma2(P, S, C4);
        P = fma2(P, S, C3);
        P = fma2(P, S, C2);
        P = fma2(P, S, C1);
        P = fma2(P, S, C0);
        ull U = pk2(u0, u1);
        ull Rp = mul2(U, P);                // 0.5 * normal (coeffs pre-scaled)
        if (fminf(l0, l1) <= LCUT) {        // rare tail (~0.7% of pairs)
            float r0, r1; upk2(r0, r1, Rp);
            if (l0 <= LCUT) r0 = tail_fix(u0, l0);
            if (l1 <= LCUT) r1 = tail_fix(u1, l1);
            Rp = pk2(r0, r1);
        }
        ull A  = h ? A23 : A01;
        ull NI = h ? NIV23 : NIV01;
        ull Q  = fma2(A, NI, ONE2);         // 1 - a/max
        R[h] = fma2(XN, A, mul2(Q, Rp));    // xn*a + q*(0.5*normal)
    }
    float4 o;
    upk2(o.x, o.y, R[0]);
    upk2(o.z, o.w, R[1]);
    out[pos + G] = o;
}

// ================= main kernel: 16 outputs (4 float4) per thread =================
__global__ void __launch_bounds__(256, 4) k_main(
    const float*  __restrict__ x,
    const float*  __restrict__ mean,
    const float*  __restrict__ stdv,
    float4*       __restrict__ out,
    unsigned one)
{
    unsigned gtid = blockIdx.x * 256u + threadIdx.x;
    unsigned pos  = gtid * 4u;                 // first (b,p) position of this thread
    unsigned p0   = pos % (unsigned)P_PAIRS;   // p0 mult of 4; p0+3 < P (P % 4 == 0)

    float4 xv = *(const float4*)(x + pos);
    float4 mu = __ldg((const float4*)(mean + p0));
    float4 sd = __ldg((const float4*)(stdv + p0));
    float xn0 = __fdividef(xv.x - mu.x, sd.x);
    float xn1 = __fdividef(xv.y - mu.y, sd.y);
    float xn2 = __fdividef(xv.z - mu.z, sd.z);
    float xn3 = __fdividef(xv.w - mu.w, sd.w);

    float4 niv4 = *(const float4*)g_negiv;
    ull NIV01 = pk2(niv4.x, niv4.y);
    ull NIV23 = pk2(niv4.z, niv4.w);

    unsigned base = gtid * 16u;                // counter base (linear index of first output)

    do_group<0>(base, one, p0, xn0, NIV01, NIV23, out, pos);
    do_group<1>(base, one, p0, xn1, NIV01, NIV23, out, pos);
    do_group<2>(base, one, p0, xn2, NIV01, NIV23, out, pos);
    do_group<3>(base, one, p0, xn3, NIV01, NIV23, out, pos);
}

// ================= launch =================
extern "C" void kernel_launch(void* const* d_in, const int* in_sizes, int n_in,
                              void* d_out, int out_size)
{
    const float* x       = (const float*)d_in[0];
    const float* mean    = (const float*)d_in[1];
    const float* stdv    = (const float*)d_in[2];
    const float* weights = (const float*)d_in[3];

    k_setup<<<(P_PAIRS + 255) / 256, 256>>>(weights);
    // positions = 256*123256 = 31,553,536; 4 per thread; /256 = 30814 blocks exact
    k_main<<<(BATCHN * P_PAIRS / 4) / 256, 256>>>(x, mean, stdv, (float4*)d_out, 1u);
    (void)in_sizes; (void)n_in; (void)out_size;
}